// round 8
// baseline (speedup 1.0000x reference)
#include <cuda_runtime.h>
#include <cuda_bf16.h>
#include <math.h>
#include <stdint.h>

// Problem constants
#define NN 100000      // nodes
#define EE 500000      // edges
#define RR 8           // relations
#define DD 128         // hidden
#define KT 1152        // Wt rows: R*D (relations) + D (root)
#define NPAIR (NN * RR)                     // 800000 (node, rel) pairs
#define TM 64                               // GEMM tile M
#define MAXBLK ((NPAIR + RR * (TM - 1) + TM - 1) / TM)   // max 64-row blocks after padding
#define NVROW (MAXBLK * TM)
#define ROOTBLK ((NN + TM - 1) / TM)        // 1563

// -------- scratch (device globals; no allocation allowed) --------
__device__ __nv_bfloat16 g_xhi[(size_t)NN * DD];
__device__ __nv_bfloat16 g_xlo[(size_t)NN * DD];
__device__ __nv_bfloat16 g_wthi[2 * (size_t)KT * DD];   // both layers
__device__ __nv_bfloat16 g_wtlo[2 * (size_t)KT * DD];
__device__ float g_out[(size_t)NN * DD];
__device__ float g_inv[NPAIR];       // 1/indeg(dst,rel)
__device__ int   g_cnt[NPAIR];       // in-degree per (dst,rel)
__device__ int   g_scnt[NPAIR];      // out-degree per (src,rel)
__device__ int   g_pos[NPAIR];       // (src,rel) -> virtual row
__device__ int   g_vnode[NVROW];     // virtual row -> node (-1 = pad)
__device__ int   g_relnz[RR];
__device__ int   g_fill[RR];
__device__ int   g_base[RR + 1];
__device__ int   g_nblk;             // active blocks
__device__ int   g_blockrel[MAXBLK];
__device__ int   g_bins[MAXBLK];
__device__ int   g_ptr[MAXBLK + 1];
__device__ int   g_cur[MAXBLK];
__device__ int   g_els[EE];          // sorted edges: local src row (pos % TM)
__device__ int   g_ed[EE];           // sorted edges: dst
__device__ float g_einv[EE];         // sorted edges: 1/cnt(dst,rel)

// ---------------- helpers ----------------
__device__ __forceinline__ uint32_t saddr(const void* p) {
    return (uint32_t)__cvta_generic_to_shared(p);
}
__device__ __forceinline__ void ldsm_x4(uint32_t* r, uint32_t addr) {
    asm volatile("ldmatrix.sync.aligned.m8n8.x4.shared.b16 {%0,%1,%2,%3}, [%4];"
                 : "=r"(r[0]), "=r"(r[1]), "=r"(r[2]), "=r"(r[3]) : "r"(addr));
}
__device__ __forceinline__ void mma_bf16(float* c, const uint32_t* a, const uint32_t* b) {
    asm volatile("mma.sync.aligned.m16n8k16.row.col.f32.bf16.bf16.f32 "
                 "{%0,%1,%2,%3}, {%4,%5,%6,%7}, {%8,%9}, {%0,%1,%2,%3};"
                 : "+f"(c[0]), "+f"(c[1]), "+f"(c[2]), "+f"(c[3])
                 : "r"(a[0]), "r"(a[1]), "r"(a[2]), "r"(a[3]), "r"(b[0]), "r"(b[1]));
}
__device__ __forceinline__ void split2(float v, __nv_bfloat16& h, __nv_bfloat16& l) {
    h = __float2bfloat16(v);
    l = __float2bfloat16(v - __bfloat162float(h));
}
__device__ __forceinline__ void red_add4(float* p, float4 v) {
    asm volatile("red.global.add.v4.f32 [%0], {%1, %2, %3, %4};"
                 :: "l"(p), "f"(v.x), "f"(v.y), "f"(v.z), "f"(v.w) : "memory");
}
__device__ __forceinline__ void red_add2(float* p, float2 v) {
    asm volatile("red.global.add.v2.f32 [%0], {%1, %2};"
                 :: "l"(p), "f"(v.x), "f"(v.y) : "memory");
}

// ---------------- fused prep: gather_split | wsplit(L1) | wsplit(L2) | hist2 ----------------
#define P_GATHER (NN * 32 / 256)                 // 12500 blocks
#define P_WS     ((KT * DD) / 256)               // 576 blocks each
#define P_HIST   ((EE + 255) / 256)              // 1954 blocks
#define PREP1_GRID (P_GATHER + 2 * P_WS + P_HIST)

__global__ void k_prep1(const int* __restrict__ ids, const float* __restrict__ emb,
                        const float* __restrict__ W1, const float* __restrict__ root1,
                        const float* __restrict__ W2, const float* __restrict__ root2,
                        const int* __restrict__ ei, const int* __restrict__ et) {
    int b = blockIdx.x;
    if (b < P_GATHER) {
        int t = b * 256 + threadIdx.x;
        int n = t >> 5, l4 = (t & 31) * 4;
        if (n >= NN) return;
        float4 v = *((const float4*)(emb + (size_t)ids[n] * DD + l4));
        __nv_bfloat16 h0, h1, h2, h3, l0, l1, l2, l3;
        split2(v.x, h0, l0); split2(v.y, h1, l1); split2(v.z, h2, l2); split2(v.w, h3, l3);
        __nv_bfloat162* ph = (__nv_bfloat162*)(g_xhi + (size_t)n * DD + l4);
        __nv_bfloat162* pl = (__nv_bfloat162*)(g_xlo + (size_t)n * DD + l4);
        ph[0] = __nv_bfloat162{h0, h1}; ph[1] = __nv_bfloat162{h2, h3};
        pl[0] = __nv_bfloat162{l0, l1}; pl[1] = __nv_bfloat162{l2, l3};
        return;
    }
    b -= P_GATHER;
    if (b < 2 * P_WS) {
        int layer = b >= P_WS;
        int t = (b - layer * P_WS) * 256 + threadIdx.x;
        const float* W     = layer ? W2 : W1;
        const float* rootM = layer ? root2 : root1;
        int loff = layer * KT * DD;
        int c = t >> 7, d = t & 127;
        float v;
        if (c < RR * DD) {
            int r = c >> 7, f = c & 127;
            v = W[((size_t)r * DD + d) * DD + f];
        } else {
            v = rootM[(size_t)d * DD + (c - RR * DD)];
        }
        __nv_bfloat16 h, l; split2(v, h, l);
        g_wthi[loff + t] = h; g_wtlo[loff + t] = l;
        return;
    }
    b -= 2 * P_WS;
    {
        int e = b * 256 + threadIdx.x;
        if (e >= EE) return;
        int src = ei[e], dst = ei[EE + e], r = et[e];
        atomicAdd(&g_cnt[dst * RR + r], 1);
        atomicAdd(&g_scnt[src * RR + r], 1);
    }
}

// inv + per-relation live-pair counts (block-aggregated atomics)
__global__ void k_inv_relnz() {
    __shared__ int c[RR];
    if (threadIdx.x < RR) c[threadIdx.x] = 0;
    __syncthreads();
    int t = blockIdx.x * blockDim.x + threadIdx.x;
    if (t < NPAIR) {
        int n = g_cnt[t];
        g_inv[t] = n > 0 ? 1.0f / (float)n : 0.0f;
        if (g_scnt[t] > 0) atomicAdd(&c[t & (RR - 1)], 1);
    }
    __syncthreads();
    if (threadIdx.x < RR && c[threadIdx.x] > 0) atomicAdd(&g_relnz[threadIdx.x], c[threadIdx.x]);
}

// bases (serial, 8 iters) + blockrel fill, single block
__global__ void k_bases_blockrel() {
    __shared__ int sbase[RR + 1];
    if (threadIdx.x == 0) {
        int b = 0;
        g_base[0] = 0; sbase[0] = 0;
        for (int r = 0; r < RR; r++) {
            b += (g_relnz[r] + TM - 1) & ~(TM - 1);
            g_base[r + 1] = b; sbase[r + 1] = b;
        }
        g_nblk = b / TM;
    }
    __syncthreads();
    for (int i = threadIdx.x; i < MAXBLK; i += blockDim.x) {
        int row = i * TM, rel = 0;
        for (int r = 0; r < RR; r++)
            if (row >= sbase[r] && row < sbase[r + 1]) rel = r;
        g_blockrel[i] = rel;
    }
}

// compact live pairs into virtual rows + accumulate per-block edge bin counts
__global__ void k_compact() {
    int t = blockIdx.x * blockDim.x + threadIdx.x;
    if (t >= NPAIR) return;
    int sc = g_scnt[t];
    if (sc > 0) {
        int node = t >> 3;              // RR == 8
        int rel  = t & 7;
        int pos = g_base[rel] + atomicAdd(&g_fill[rel], 1);
        g_vnode[pos] = node;
        g_pos[t] = pos;
        atomicAdd(&g_bins[pos / TM], sc);   // bin size = sum of out-degrees
    }
}

// single-block exclusive scan over MAXBLK bins
__global__ void k_scan() {
    __shared__ int wsum[32];
    const int tid = threadIdx.x;
    const int per = (MAXBLK + 1023) / 1024;
    int base = tid * per;
    int loc[16]; int s = 0;
    for (int i = 0; i < per; i++) {
        int idx = base + i;
        int v = (idx < MAXBLK) ? g_bins[idx] : 0;
        loc[i] = s; s += v;
    }
    int lane = tid & 31, wid = tid >> 5;
    int x = s;
    for (int d = 1; d < 32; d <<= 1) {
        int y = __shfl_up_sync(0xffffffffu, x, d);
        if (lane >= d) x += y;
    }
    if (lane == 31) wsum[wid] = x;
    __syncthreads();
    if (wid == 0) {
        int y = wsum[lane];
        for (int d = 1; d < 32; d <<= 1) {
            int z = __shfl_up_sync(0xffffffffu, y, d);
            if (lane >= d) y += z;
        }
        wsum[lane] = y;
    }
    __syncthreads();
    int excl = x - s + (wid > 0 ? wsum[wid - 1] : 0);
    for (int i = 0; i < per; i++) {
        int idx = base + i;
        if (idx < MAXBLK) { int p = excl + loc[i]; g_ptr[idx] = p; g_cur[idx] = p; }
    }
    if (tid == 1023) g_ptr[MAXBLK] = excl + s;
}

__global__ void k_eperm(const int* __restrict__ ei, const int* __restrict__ et) {
    int e = blockIdx.x * blockDim.x + threadIdx.x;
    if (e >= EE) return;
    int src = ei[e], dst = ei[EE + e], r = et[e];
    int pos = g_pos[src * RR + r];
    int i = atomicAdd(&g_cur[pos / TM], 1);
    g_els[i]  = pos % TM;
    g_ed[i]   = dst;
    g_einv[i] = g_inv[dst * RR + r];
}

// ---------------- combined GEMM (rel blocks first, then root blocks) ----------------
// g_out MUST be zeroed before this launch; BOTH paths accumulate via red.add,
// making rel/root CTA interleaving order-independent (fixes the R7 race).
#define PADK 136
#define GSM_AH 0
#define GSM_AL 17408
#define GSM_BH 34816
#define GSM_BL 69632
#define GSM_TOTAL 104448     // per-CTA dynamic smem; 2 CTAs/SM

// MMA core: 64(M) x 128(N) x 128(K), warps 2(M) x 4(N), warp tile 32x32
#define MMA_CORE(Ah, Al, Bh, Bl, acc)                                              \
    {                                                                              \
        _Pragma("unroll")                                                          \
        for (int ks = 0; ks < 8; ks++) {                                           \
            const int k0 = ks * 16;                                                \
            uint32_t ah[2][4], al[2][4];                                           \
            _Pragma("unroll")                                                      \
            for (int mf = 0; mf < 2; mf++) {                                       \
                ldsm_x4(ah[mf], saddr(Ah + (a_row + mf * 16) * PADK + k0 + a_koff));\
                ldsm_x4(al[mf], saddr(Al + (a_row + mf * 16) * PADK + k0 + a_koff));\
            }                                                                      \
            _Pragma("unroll")                                                      \
            for (int np = 0; np < 2; np++) {                                       \
                uint32_t bh[4], bl[4];                                             \
                ldsm_x4(bh, saddr(Bh + (b_nrow + np * 16) * PADK + k0 + b_koff));  \
                ldsm_x4(bl, saddr(Bl + (b_nrow + np * 16) * PADK + k0 + b_koff));  \
                _Pragma("unroll")                                                  \
                for (int sub = 0; sub < 2; sub++) {                                \
                    uint32_t bfh[2] = { bh[sub], bh[sub + 2] };                    \
                    uint32_t bfl[2] = { bl[sub], bl[sub + 2] };                    \
                    _Pragma("unroll")                                              \
                    for (int mf = 0; mf < 2; mf++) {                               \
                        float* c = acc[mf][np * 2 + sub];                          \
                        mma_bf16(c, ah[mf], bfh);                                  \
                        mma_bf16(c, ah[mf], bfl);                                  \
                        mma_bf16(c, al[mf], bfh);                                  \
                    }                                                              \
                }                                                                  \
            }                                                                      \
        }                                                                          \
    }

__global__ __launch_bounds__(256, 2)
void k_gemm_all(int loff) {
    extern __shared__ char sm[];
    __nv_bfloat16* Ah = (__nv_bfloat16*)(sm + GSM_AH);
    __nv_bfloat16* Al = (__nv_bfloat16*)(sm + GSM_AL);
    __nv_bfloat16* Bh = (__nv_bfloat16*)(sm + GSM_BH);
    __nv_bfloat16* Bl = (__nv_bfloat16*)(sm + GSM_BL);
    float*         hsm = (float*)(sm + GSM_BH);   // aliases B after MMA (rel path)

    const int tid  = threadIdx.x;
    const int lane = tid & 31, warp = tid >> 5;

    const bool isRel = (int)blockIdx.x < MAXBLK;
    if (isRel && (int)blockIdx.x >= g_nblk) return;

    const int brow = isRel ? g_blockrel[blockIdx.x] : RR;   // B row-block in Wt
    const int row0 = isRel ? (int)blockIdx.x * TM : ((int)blockIdx.x - MAXBLK) * TM;

    // ---- load A ----
    for (int v = tid; v < 1024; v += 256) {
        int r = v >> 4, c8 = (v & 15) << 3;
        int node;
        if (isRel) node = g_vnode[row0 + r];
        else       node = (row0 + r < NN) ? row0 + r : -1;
        uint4 h = make_uint4(0, 0, 0, 0), l = make_uint4(0, 0, 0, 0);
        if (node >= 0) {
            h = *(const uint4*)(g_xhi + (size_t)node * DD + c8);
            l = *(const uint4*)(g_xlo + (size_t)node * DD + c8);
        }
        *(uint4*)(Ah + r * PADK + c8) = h;
        *(uint4*)(Al + r * PADK + c8) = l;
    }
    // ---- load B ----
    for (int v = tid; v < 2048; v += 256) {
        int r = v >> 4, c8 = (v & 15) << 3;
        const size_t gofs = (size_t)loff + (size_t)(brow * DD + r) * DD + c8;
        *(uint4*)(Bh + r * PADK + c8) = *(const uint4*)(g_wthi + gofs);
        *(uint4*)(Bl + r * PADK + c8) = *(const uint4*)(g_wtlo + gofs);
    }
    __syncthreads();

    const int wm = warp & 1, wn = warp >> 1;
    const int a_row  = wm * 32 + (lane & 15);
    const int a_koff = (lane >> 4) * 8;
    const int b_nrow = wn * 32 + (lane & 7) + ((lane >> 3) & 1) * 8;
    const int b_koff = (lane >> 4) * 8;

    float acc[2][4][4];
#pragma unroll
    for (int i = 0; i < 2; i++)
#pragma unroll
        for (int j = 0; j < 4; j++)
#pragma unroll
            for (int k = 0; k < 4; k++) acc[i][j][k] = 0.f;

    MMA_CORE(Ah, Al, Bh, Bl, acc)

    if (!isRel) {
        // root path: accumulate into pre-zeroed g_out (race-free vs rel scatter)
#pragma unroll
        for (int mf = 0; mf < 2; mf++) {
#pragma unroll
            for (int nf = 0; nf < 4; nf++) {
                int r = row0 + wm * 32 + mf * 16 + (lane >> 2);
                int c = wn * 32 + nf * 8 + (lane & 3) * 2;
                float* cc = acc[mf][nf];
                if (r < NN)
                    red_add2(g_out + (size_t)r * DD + c, make_float2(cc[0], cc[1]));
                if (r + 8 < NN)
                    red_add2(g_out + (size_t)(r + 8) * DD + c, make_float2(cc[2], cc[3]));
            }
        }
        return;
    }

    __syncthreads();   // all warps done reading B before hsm overwrites it

    // h tile -> smem (aliased over B)
#pragma unroll
    for (int mf = 0; mf < 2; mf++) {
#pragma unroll
        for (int nf = 0; nf < 4; nf++) {
            int r = wm * 32 + mf * 16 + (lane >> 2);
            int c = wn * 32 + nf * 8 + (lane & 3) * 2;
            float* cc = acc[mf][nf];
            *(float2*)(hsm + r * 128 + c)       = make_float2(cc[0], cc[1]);
            *(float2*)(hsm + (r + 8) * 128 + c) = make_float2(cc[2], cc[3]);
        }
    }
    __syncthreads();

    // scatter this block's edges (one warp per edge)
    int s = g_ptr[blockIdx.x], e2 = g_ptr[blockIdx.x + 1];
    for (int i = s + warp; i < e2; i += 8) {
        int   ls  = g_els[i];
        int   dst = g_ed[i];
        float inv = g_einv[i];
        float4 v = *(const float4*)(hsm + ls * 128 + lane * 4);
        v.x *= inv; v.y *= inv; v.z *= inv; v.w *= inv;
        red_add4(g_out + (size_t)dst * DD + lane * 4, v);
    }
}

// ---------------- activations (bias folded in) ----------------
__global__ void k_act_relu(const float* __restrict__ bias) {
    int t = blockIdx.x * blockDim.x + threadIdx.x;
    if (t >= NN * 32) return;
    float4 v = *(const float4*)(g_out + (size_t)t * 4);
    float4 b = __ldg((const float4*)(bias + (t & 31) * 4));
    v.x = fmaxf(v.x + b.x, 0.f); v.y = fmaxf(v.y + b.y, 0.f);
    v.z = fmaxf(v.z + b.z, 0.f); v.w = fmaxf(v.w + b.w, 0.f);
    __nv_bfloat16 h0, h1, h2, h3, l0, l1, l2, l3;
    split2(v.x, h0, l0); split2(v.y, h1, l1); split2(v.z, h2, l2); split2(v.w, h3, l3);
    __nv_bfloat162* ph = (__nv_bfloat162*)(g_xhi + (size_t)t * 4);
    __nv_bfloat162* pl = (__nv_bfloat162*)(g_xlo + (size_t)t * 4);
    ph[0] = __nv_bfloat162{h0, h1}; ph[1] = __nv_bfloat162{h2, h3};
    pl[0] = __nv_bfloat162{l0, l1}; pl[1] = __nv_bfloat162{l2, l3};
}

__global__ void k_sigmoid(const float* __restrict__ bias, float* __restrict__ outp) {
    int t = blockIdx.x * blockDim.x + threadIdx.x;
    if (t >= NN * 32) return;
    float4 v = *(const float4*)(g_out + (size_t)t * 4);
    float4 b = __ldg((const float4*)(bias + (t & 31) * 4));
    v.x = 1.0f / (1.0f + __expf(-(v.x + b.x)));
    v.y = 1.0f / (1.0f + __expf(-(v.y + b.y)));
    v.z = 1.0f / (1.0f + __expf(-(v.z + b.z)));
    v.w = 1.0f / (1.0f + __expf(-(v.w + b.w)));
    *(float4*)(outp + (size_t)t * 4) = v;
}

// ---------------- launch ----------------
extern "C" void kernel_launch(void* const* d_in, const int* in_sizes, int n_in,
                              void* d_out, int out_size) {
    const int*   x_ids = (const int*)  d_in[0];
    const int*   ei    = (const int*)  d_in[1];   // [2, E]: src row then dst row
    const int*   et    = (const int*)  d_in[2];
    const float* emb   = (const float*)d_in[3];
    const float* W1    = (const float*)d_in[4];
    const float* root1 = (const float*)d_in[5];
    const float* b1    = (const float*)d_in[6];
    const float* W2    = (const float*)d_in[7];
    const float* root2 = (const float*)d_in[8];
    const float* b2    = (const float*)d_in[9];
    float*       out   = (float*)d_out;
    (void)in_sizes; (void)n_in; (void)out_size;

    cudaFuncSetAttribute(k_gemm_all, cudaFuncAttributeMaxDynamicSharedMemorySize, GSM_TOTAL);

    void *p_cnt, *p_scnt, *p_relnz, *p_fill, *p_bins, *p_vnode, *p_out;
    cudaGetSymbolAddress(&p_cnt,   g_cnt);
    cudaGetSymbolAddress(&p_scnt,  g_scnt);
    cudaGetSymbolAddress(&p_relnz, g_relnz);
    cudaGetSymbolAddress(&p_fill,  g_fill);
    cudaGetSymbolAddress(&p_bins,  g_bins);
    cudaGetSymbolAddress(&p_vnode, g_vnode);
    cudaGetSymbolAddress(&p_out,   g_out);

    const int T = 256;

    // ---- zero/init (async memsets; g_vnode = 0xFF.. == -1) ----
    cudaMemsetAsync(p_cnt,   0,    NPAIR * sizeof(int));
    cudaMemsetAsync(p_scnt,  0,    NPAIR * sizeof(int));
    cudaMemsetAsync(p_relnz, 0,    RR * sizeof(int));
    cudaMemsetAsync(p_fill,  0,    RR * sizeof(int));
    cudaMemsetAsync(p_bins,  0,    MAXBLK * sizeof(int));
    cudaMemsetAsync(p_vnode, 0xFF, NVROW * sizeof(int));
    cudaMemsetAsync(p_out,   0,    (size_t)NN * DD * sizeof(float));

    // ---- prep ----
    k_prep1<<<PREP1_GRID, T>>>(x_ids, emb, W1, root1, W2, root2, ei, et);
    k_inv_relnz<<<(NPAIR + T - 1) / T, T>>>();
    k_bases_blockrel<<<1, 1024>>>();
    k_compact<<<(NPAIR + T - 1) / T, T>>>();
    k_scan<<<1, 1024>>>();
    k_eperm<<<(EE + T - 1) / T, T>>>(ei, et);

    const int allBlocks = MAXBLK + ROOTBLK;   // rel blocks first, then root

    // ---- layer 1 ----
    k_gemm_all<<<allBlocks, 256, GSM_TOTAL>>>(0);
    k_act_relu<<<(NN * 32) / T, T>>>(b1);

    // ---- layer 2 ----
    cudaMemsetAsync(p_out, 0, (size_t)NN * DD * sizeof(float));
    k_gemm_all<<<allBlocks, 256, GSM_TOTAL>>>(KT * DD);
    k_sigmoid<<<(NN * 32) / T, T>>>(b2, out);
}